// round 7
// baseline (speedup 1.0000x reference)
#include <cuda_runtime.h>

// Problem constants (fixed by the dataset shapes)
#define B_      8
#define NHEADS  4
#define Q_      512      // codebook entries per head (N/4)
#define L_      2048     // sequence length (innermost logits dim)
#define D_      512      // embedding dim
#define K_      3        // top-k

#define LT       32      // l-tile per block
#define NTHREADS 512
#define SEGS     4       // n-range split per (h,l)
#define NSEG     (Q_ / SEGS)   // 128

#define DCHUNK   128             // dd per phase-2 round (float4: 32 lanes x 4)
#define NROUND   (D_ / DCHUNK)   // 4
#define TPITCH   132             // tile row pitch in floats (16B-aligned, 132 mod 32 = 4)

// top-3 update, branch-light common path (v <= t2 almost always)
#define TOP3_UPDATE(v, n)                                              \
    do {                                                               \
        if ((v) > t2) {                                                \
            if ((v) > t0)      { t2=t1; i2=i1; t1=t0; i1=i0; t0=(v); i0=(n); } \
            else if ((v) > t1) { t2=t1; i2=i1; t1=(v); i1=(n); }       \
            else               { t2=(v); i2=(n); }                     \
        }                                                              \
    } while (0)

__global__ __launch_bounds__(NTHREADS)
void embed_topk_combine(const float* __restrict__ logits,
                        const float* __restrict__ e0,
                        const float* __restrict__ e1,
                        const float* __restrict__ e2,
                        const float* __restrict__ e3,
                        float* __restrict__ out)
{
    const int b   = blockIdx.y;
    const int l0  = blockIdx.x * LT;
    const int tid = threadIdx.x;

    // Overlaid SMEM region:
    //   phase 1: partial top-3 from segments 1..3   (2 x 4608 B = 9216 B)
    //   phase 2: 32 x TPITCH float transpose tile   (16896 B)
    // Lifetimes are disjoint (partials dead after the merge barrier).
    __shared__ __align__(16) char s_buf[32 * TPITCH * 4];
    float* s_pv  = (float*)s_buf;                    // [3][NHEADS][LT][K_]
    int*   s_pi  = (int*)(s_buf + (SEGS-1)*NHEADS*LT*K_*4);
    float* tile  = (float*)s_buf;                    // [LT][TPITCH]

    // merged result (persists through phase 2)
    __shared__ int   s_idx[NHEADS][LT][K_];
    __shared__ float s_w  [NHEADS][LT][K_];

    // ---------------- phase 1: split-n top-3 (MLP=8 per thread) ----------
    {
        const int l   = tid & (LT - 1);            // 0..31
        const int h   = (tid >> 5) & (NHEADS - 1); // 0..3
        const int seg = tid >> 7;                  // 0..3
        const int nb  = seg * NSEG;

        const float* p = logits
            + ((size_t)b * (NHEADS * Q_) + (size_t)h * Q_ + nb) * L_ + l0 + l;

        float t0 = -3.4e38f, t1 = -3.4e38f, t2 = -3.4e38f;
        int   i0 = 0, i1 = 0, i2 = 0;

        for (int n = 0; n < NSEG; n += 8) {
            float v0 = __ldg(p + (size_t)(n + 0) * L_);
            float v1 = __ldg(p + (size_t)(n + 1) * L_);
            float v2 = __ldg(p + (size_t)(n + 2) * L_);
            float v3 = __ldg(p + (size_t)(n + 3) * L_);
            float v4 = __ldg(p + (size_t)(n + 4) * L_);
            float v5 = __ldg(p + (size_t)(n + 5) * L_);
            float v6 = __ldg(p + (size_t)(n + 6) * L_);
            float v7 = __ldg(p + (size_t)(n + 7) * L_);
            TOP3_UPDATE(v0, nb + n + 0);
            TOP3_UPDATE(v1, nb + n + 1);
            TOP3_UPDATE(v2, nb + n + 2);
            TOP3_UPDATE(v3, nb + n + 3);
            TOP3_UPDATE(v4, nb + n + 4);
            TOP3_UPDATE(v5, nb + n + 5);
            TOP3_UPDATE(v6, nb + n + 6);
            TOP3_UPDATE(v7, nb + n + 7);
        }

        if (seg > 0) {
            int base = (((seg - 1) * NHEADS + h) * LT + l) * K_;
            s_pv[base + 0] = t0;  s_pi[base + 0] = i0;
            s_pv[base + 1] = t1;  s_pi[base + 1] = i1;
            s_pv[base + 2] = t2;  s_pi[base + 2] = i2;
        }
        __syncthreads();

        if (seg == 0) {
            #pragma unroll
            for (int s = 0; s < SEGS - 1; s++) {
                int base = ((s * NHEADS + h) * LT + l) * K_;
                #pragma unroll
                for (int k = 0; k < K_; k++) {
                    float v = s_pv[base + k];
                    int   n = s_pi[base + k];
                    TOP3_UPDATE(v, n);
                }
            }
            float w1  = expf(t1 - t0);
            float w2  = expf(t2 - t0);
            float inv = 1.0f / (1.0f + w1 + w2);
            s_w[h][l][0] = inv;
            s_w[h][l][1] = w1 * inv;
            s_w[h][l][2] = w2 * inv;
            s_idx[h][l][0] = i0;
            s_idx[h][l][1] = i1;
            s_idx[h][l][2] = i2;
        }
    }
    __syncthreads();   // also fences partials before the tile overlays them

    // ---------------- phase 2: float4 gather-combine, 4 rounds -----------
    const int warp = tid >> 5;   // 0..15
    const int lane = tid & 31;
    float* outb = out + (size_t)b * D_ * L_ + l0;

    const float4* t0_4 = (const float4*)e0;
    const float4* t1_4 = (const float4*)e1;
    const float4* t2_4 = (const float4*)e2;
    const float4* t3_4 = (const float4*)e3;

    #pragma unroll
    for (int r = 0; r < NROUND; r++) {
        const int c = r * (DCHUNK / 4) + lane;   // float4 column within row

        // warp <-> li: 12 independent LDG.128 per li (512B lines each)
        #pragma unroll
        for (int li = warp; li < LT; li += NTHREADS / 32) {
            float4 acc = make_float4(0.f, 0.f, 0.f, 0.f);
            #pragma unroll
            for (int h = 0; h < NHEADS; h++) {
                const float4* eh = (h == 0) ? t0_4 : (h == 1) ? t1_4
                                 : (h == 2) ? t2_4 : t3_4;
                #pragma unroll
                for (int k = 0; k < K_; k++) {
                    int    m = s_idx[h][li][k];
                    float  w = s_w  [h][li][k];
                    float4 v = __ldg(eh + (size_t)m * (D_ / 4) + c);
                    acc.x = fmaf(w, v.x, acc.x);
                    acc.y = fmaf(w, v.y, acc.y);
                    acc.z = fmaf(w, v.z, acc.z);
                    acc.w = fmaf(w, v.w, acc.w);
                }
            }
            // conflict-free float4 store: row li, cols 4*lane..4*lane+3
            *(float4*)&tile[li * TPITCH + 4 * lane] = acc;
        }
        __syncthreads();

        // coalesced output: lane <-> l, warp-strided over dd
        #pragma unroll
        for (int i = tid; i < DCHUNK * LT; i += NTHREADS) {
            int dd = i >> 5;         // 0..127
            int l  = i & (LT - 1);
            outb[(size_t)(r * DCHUNK + dd) * L_ + l] = tile[l * TPITCH + dd];
        }
        __syncthreads();
    }
}

extern "C" void kernel_launch(void* const* d_in, const int* in_sizes, int n_in,
                              void* d_out, int out_size)
{
    const float* logits = (const float*)d_in[0];
    const float* e0     = (const float*)d_in[1];
    const float* e1     = (const float*)d_in[2];
    const float* e2     = (const float*)d_in[3];
    const float* e3     = (const float*)d_in[4];
    float*       out    = (float*)d_out;

    dim3 grid(L_ / LT, B_);   // 64 x 8 = 512 blocks
    dim3 block(NTHREADS);
    embed_topk_combine<<<grid, block>>>(logits, e0, e1, e2, e3, out);
}

// round 8
// speedup vs baseline: 1.1124x; 1.1124x over previous
#include <cuda_runtime.h>

// Problem constants (fixed by the dataset shapes)
#define B_      8
#define NHEADS  4
#define Q_      512      // codebook entries per head (N/4)
#define L_      2048     // sequence length (innermost logits dim)
#define D_      512      // embedding dim
#define K_      3        // top-k

#define LT       32      // l-tile per block
#define NTHREADS 512
#define SEGS     4       // n-range split per (h,l)
#define NSEG     (Q_ / SEGS)   // 128

#define DCHUNK   256             // dd per phase-2 round
#define NROUND   (D_ / DCHUNK)   // 2
#define TPITCH   260             // tile row pitch in floats (16B aligned)

// top-3 update, branch-light common path (v <= t2 almost always)
#define TOP3_UPDATE(v, n)                                              \
    do {                                                               \
        if ((v) > t2) {                                                \
            if ((v) > t0)      { t2=t1; i2=i1; t1=t0; i1=i0; t0=(v); i0=(n); } \
            else if ((v) > t1) { t2=t1; i2=i1; t1=(v); i1=(n); }       \
            else               { t2=(v); i2=(n); }                     \
        }                                                              \
    } while (0)

__global__ __launch_bounds__(NTHREADS, 3)
void embed_topk_combine(const float* __restrict__ logits,
                        const float* __restrict__ e0,
                        const float* __restrict__ e1,
                        const float* __restrict__ e2,
                        const float* __restrict__ e3,
                        float* __restrict__ out)
{
    const int b   = blockIdx.y;
    const int l0  = blockIdx.x * LT;
    const int tid = threadIdx.x;

    // Overlaid SMEM region:
    //   phase 1: partial top-3 from segments 1..3   (9216 B)
    //   phase 2: LT x TPITCH float transpose tile   (33280 B)
    // Lifetimes are disjoint (partials dead after the merge barrier).
    __shared__ __align__(16) char s_buf[LT * TPITCH * 4];
    float* s_pv  = (float*)s_buf;                    // [3][NHEADS][LT][K_]
    int*   s_pi  = (int*)(s_buf + (SEGS-1)*NHEADS*LT*K_*4);
    float* tile  = (float*)s_buf;                    // [LT][TPITCH]

    // merged result (persists through phase 2); idx pre-scaled to float4-row base
    __shared__ int   s_idx[NHEADS][LT][K_];
    __shared__ float s_w  [NHEADS][LT][K_];

    // ---------------- phase 1: split-n top-3 (MLP=8 per thread) ----------
    {
        const int l   = tid & (LT - 1);            // 0..31
        const int h   = (tid >> 5) & (NHEADS - 1); // 0..3
        const int seg = tid >> 7;                  // 0..3
        const int nb  = seg * NSEG;

        const float* p = logits
            + ((size_t)b * (NHEADS * Q_) + (size_t)h * Q_ + nb) * L_ + l0 + l;

        float t0 = -3.4e38f, t1 = -3.4e38f, t2 = -3.4e38f;
        int   i0 = 0, i1 = 0, i2 = 0;

        for (int n = 0; n < NSEG; n += 8) {
            float v0 = __ldg(p + (size_t)(n + 0) * L_);
            float v1 = __ldg(p + (size_t)(n + 1) * L_);
            float v2 = __ldg(p + (size_t)(n + 2) * L_);
            float v3 = __ldg(p + (size_t)(n + 3) * L_);
            float v4 = __ldg(p + (size_t)(n + 4) * L_);
            float v5 = __ldg(p + (size_t)(n + 5) * L_);
            float v6 = __ldg(p + (size_t)(n + 6) * L_);
            float v7 = __ldg(p + (size_t)(n + 7) * L_);
            TOP3_UPDATE(v0, nb + n + 0);
            TOP3_UPDATE(v1, nb + n + 1);
            TOP3_UPDATE(v2, nb + n + 2);
            TOP3_UPDATE(v3, nb + n + 3);
            TOP3_UPDATE(v4, nb + n + 4);
            TOP3_UPDATE(v5, nb + n + 5);
            TOP3_UPDATE(v6, nb + n + 6);
            TOP3_UPDATE(v7, nb + n + 7);
        }

        if (seg > 0) {
            int base = (((seg - 1) * NHEADS + h) * LT + l) * K_;
            s_pv[base + 0] = t0;  s_pi[base + 0] = i0;
            s_pv[base + 1] = t1;  s_pi[base + 1] = i1;
            s_pv[base + 2] = t2;  s_pi[base + 2] = i2;
        }
        __syncthreads();

        if (seg == 0) {
            #pragma unroll
            for (int s = 0; s < SEGS - 1; s++) {
                int base = ((s * NHEADS + h) * LT + l) * K_;
                #pragma unroll
                for (int k = 0; k < K_; k++) {
                    float v = s_pv[base + k];
                    int   n = s_pi[base + k];
                    TOP3_UPDATE(v, n);
                }
            }
            float w1  = expf(t1 - t0);
            float w2  = expf(t2 - t0);
            float inv = 1.0f / (1.0f + w1 + w2);
            s_w[h][l][0] = inv;
            s_w[h][l][1] = w1 * inv;
            s_w[h][l][2] = w2 * inv;
            // pre-scale index to float4-row offset (row = m * D_/4)
            s_idx[h][l][0] = i0 * (D_ / 4);
            s_idx[h][l][1] = i1 * (D_ / 4);
            s_idx[h][l][2] = i2 * (D_ / 4);
        }
    }
    __syncthreads();   // also fences partials before the tile overlays them

    // ---------------- phase 2: vec4 gather-combine, 2 big rounds ----------
    const int warp = tid >> 5;   // 0..15
    const int lane = tid & 31;
    float* outb = out + (size_t)b * D_ * L_ + l0;

    const float4* eh4[NHEADS] = { (const float4*)e0, (const float4*)e1,
                                  (const float4*)e2, (const float4*)e3 };

    #pragma unroll
    for (int r = 0; r < NROUND; r++) {
        const int cbase = r * (DCHUNK / 4);   // float4 column base of this round

        // warp <-> li (2 per warp): per row two LDG.128, 8-float accumulator
        for (int li = warp; li < LT; li += NTHREADS / 32) {
            float4 a0 = make_float4(0.f, 0.f, 0.f, 0.f);
            float4 a1 = make_float4(0.f, 0.f, 0.f, 0.f);
            #pragma unroll
            for (int h = 0; h < NHEADS; h++) {
                const float4* eh = eh4[h];
                #pragma unroll
                for (int k = 0; k < K_; k++) {
                    int    mo = s_idx[h][li][k];          // already *D_/4
                    float  w  = s_w  [h][li][k];
                    float4 va = __ldg(eh + mo + cbase + lane);
                    float4 vb = __ldg(eh + mo + cbase + lane + 32);
                    a0.x = fmaf(w, va.x, a0.x);  a0.y = fmaf(w, va.y, a0.y);
                    a0.z = fmaf(w, va.z, a0.z);  a0.w = fmaf(w, va.w, a0.w);
                    a1.x = fmaf(w, vb.x, a1.x);  a1.y = fmaf(w, vb.y, a1.y);
                    a1.z = fmaf(w, vb.z, a1.z);  a1.w = fmaf(w, vb.w, a1.w);
                }
            }
            // STS.128: sequential 16B per lane -> conflict-free
            *(float4*)&tile[li * TPITCH + 4 * lane]       = a0;
            *(float4*)&tile[li * TPITCH + 4 * lane + 128] = a1;
        }
        __syncthreads();

        // coalesced output: lane <-> l; 16 dd's per thread
        const int l = lane;
        #pragma unroll
        for (int j = 0; j < DCHUNK / 16; j++) {
            int ddl = (tid >> 5) + j * 16;   // 0..255 local dd
            outb[(size_t)(r * DCHUNK + ddl) * L_ + l] = tile[l * TPITCH + ddl];
        }
        __syncthreads();
    }
}

extern "C" void kernel_launch(void* const* d_in, const int* in_sizes, int n_in,
                              void* d_out, int out_size)
{
    const float* logits = (const float*)d_in[0];
    const float* e0     = (const float*)d_in[1];
    const float* e1     = (const float*)d_in[2];
    const float* e2     = (const float*)d_in[3];
    const float* e3     = (const float*)d_in[4];
    float*       out    = (float*)d_out;

    dim3 grid(L_ / LT, B_);   // 64 x 8 = 512 blocks
    dim3 block(NTHREADS);
    embed_topk_combine<<<grid, block>>>(logits, e0, e1, e2, e3, out);
}

// round 12
// speedup vs baseline: 1.6804x; 1.5106x over previous
#include <cuda_runtime.h>

// Problem constants (fixed by the dataset shapes)
#define B_      8
#define NHEADS  4
#define Q_      512      // codebook entries per head (N/4)
#define L_      2048     // sequence length (innermost logits dim)
#define D_      512      // embedding dim
#define K_      3        // top-k

// ---------------- kernel A config ----------------
#define LTA      32      // l-tile per block
#define NTHRA    512
#define SEGS     4       // n-range split per (h,l)
#define NSEG     (Q_ / SEGS)   // 128

// ---------------- kernel B config ----------------
#define LTB      32              // l-tile per block
#define NTHRB    256             // 8 warps
#define DCHUNK   128             // dd per round (float4: 32 lanes x 4)
#define NROUND   (D_ / DCHUNK)   // 4
#define TPITCH   132             // tile pitch in floats (16B-aligned)

// Scratch: (idx pre-scaled to float4 row base, w) per (b,h,l,k). 1.5 MB total.
__device__ int   g_idx[B_ * NHEADS * L_ * K_];
__device__ float g_w  [B_ * NHEADS * L_ * K_];

// top-3 update, branch-light common path (v <= t2 almost always)
#define TOP3_UPDATE(v, n)                                              \
    do {                                                               \
        if ((v) > t2) {                                                \
            if ((v) > t0)      { t2=t1; i2=i1; t1=t0; i1=i0; t0=(v); i0=(n); } \
            else if ((v) > t1) { t2=t1; i2=i1; t1=(v); i1=(n); }       \
            else               { t2=(v); i2=(n); }                     \
        }                                                              \
    } while (0)

// ======================= kernel A: top-3 + softmax =======================
__global__ __launch_bounds__(NTHRA)
void topk_softmax(const float* __restrict__ logits)
{
    const int b   = blockIdx.y;
    const int l0  = blockIdx.x * LTA;
    const int tid = threadIdx.x;

    // partial top-3 from segments 1..3 (segment 0 stays in the merger's regs)
    __shared__ float s_pv[SEGS - 1][NHEADS][LTA][K_];
    __shared__ int   s_pi[SEGS - 1][NHEADS][LTA][K_];

    const int l   = tid & (LTA - 1);           // 0..31
    const int h   = (tid >> 5) & (NHEADS - 1); // 0..3
    const int seg = tid >> 7;                  // 0..3
    const int nb  = seg * NSEG;

    const float* p = logits
        + ((size_t)b * (NHEADS * Q_) + (size_t)h * Q_ + nb) * L_ + l0 + l;

    float t0 = -3.4e38f, t1 = -3.4e38f, t2 = -3.4e38f;
    int   i0 = 0, i1 = 0, i2 = 0;

    // 8-wide load batching: 8 independent 128B lines in flight per warp batch
    for (int n = 0; n < NSEG; n += 8) {
        float v0 = __ldg(p + (size_t)(n + 0) * L_);
        float v1 = __ldg(p + (size_t)(n + 1) * L_);
        float v2 = __ldg(p + (size_t)(n + 2) * L_);
        float v3 = __ldg(p + (size_t)(n + 3) * L_);
        float v4 = __ldg(p + (size_t)(n + 4) * L_);
        float v5 = __ldg(p + (size_t)(n + 5) * L_);
        float v6 = __ldg(p + (size_t)(n + 6) * L_);
        float v7 = __ldg(p + (size_t)(n + 7) * L_);
        TOP3_UPDATE(v0, nb + n + 0);
        TOP3_UPDATE(v1, nb + n + 1);
        TOP3_UPDATE(v2, nb + n + 2);
        TOP3_UPDATE(v3, nb + n + 3);
        TOP3_UPDATE(v4, nb + n + 4);
        TOP3_UPDATE(v5, nb + n + 5);
        TOP3_UPDATE(v6, nb + n + 6);
        TOP3_UPDATE(v7, nb + n + 7);
    }

    if (seg > 0) {
        s_pv[seg - 1][h][l][0] = t0;  s_pi[seg - 1][h][l][0] = i0;
        s_pv[seg - 1][h][l][1] = t1;  s_pi[seg - 1][h][l][1] = i1;
        s_pv[seg - 1][h][l][2] = t2;  s_pi[seg - 1][h][l][2] = i2;
    }
    __syncthreads();

    if (seg == 0) {
        #pragma unroll
        for (int s = 0; s < SEGS - 1; s++) {
            #pragma unroll
            for (int k = 0; k < K_; k++) {
                float v = s_pv[s][h][l][k];
                int   n = s_pi[s][h][l][k];
                TOP3_UPDATE(v, n);
            }
        }
        float w1  = expf(t1 - t0);
        float w2  = expf(t2 - t0);
        float inv = 1.0f / (1.0f + w1 + w2);

        size_t base = (((size_t)b * NHEADS + h) * L_ + (l0 + l)) * K_;
        g_w[base + 0] = inv;
        g_w[base + 1] = w1 * inv;
        g_w[base + 2] = w2 * inv;
        // pre-scale index to float4-row offset (row = m * D_/4)
        g_idx[base + 0] = i0 * (D_ / 4);
        g_idx[base + 1] = i1 * (D_ / 4);
        g_idx[base + 2] = i2 * (D_ / 4);
    }
}

// =============== kernel B: gather-combine + transpose-out ===============
__global__ __launch_bounds__(NTHRB)
void gather_combine(const float* __restrict__ e0,
                    const float* __restrict__ e1,
                    const float* __restrict__ e2,
                    const float* __restrict__ e3,
                    float* __restrict__ out)
{
    const int b   = blockIdx.y;
    const int l0  = blockIdx.x * LTB;
    const int tid = threadIdx.x;

    __shared__ int   s_idx[NHEADS][LTB][K_];     // 384 ints
    __shared__ float s_w  [NHEADS][LTB][K_];     // 384 floats
    __shared__ __align__(16) float tile[LTB][TPITCH];

    // stage this block's (idx, w): 384 entries, grid-stride over 256 threads
    // (R11 bug: plain `if (tid < 384)` left entries 256..383 uninitialized)
    for (int i = tid; i < NHEADS * LTB * K_; i += NTHRB) {
        int h  = i / (LTB * K_);
        int r  = i - h * (LTB * K_);
        size_t g = (((size_t)b * NHEADS + h) * L_ + l0) * K_ + r;
        ((int*)  s_idx)[i] = g_idx[g];
        ((float*)s_w  )[i] = g_w  [g];
    }
    __syncthreads();

    const int warp = tid >> 5;   // 0..7
    const int lane = tid & 31;
    float* outb = out + (size_t)b * D_ * L_ + l0;

    const float4* eh4[NHEADS] = { (const float4*)e0, (const float4*)e1,
                                  (const float4*)e2, (const float4*)e3 };

    #pragma unroll
    for (int r = 0; r < NROUND; r++) {
        const int c = r * (DCHUNK / 4) + lane;   // float4 column

        // warp <-> li (4 per warp): 12 independent LDG.128 per li
        #pragma unroll
        for (int li = warp; li < LTB; li += NTHRB / 32) {
            float4 acc = make_float4(0.f, 0.f, 0.f, 0.f);
            #pragma unroll
            for (int h = 0; h < NHEADS; h++) {
                const float4* eh = eh4[h];
                #pragma unroll
                for (int k = 0; k < K_; k++) {
                    int    mo = s_idx[h][li][k];    // already * D_/4
                    float  w  = s_w  [h][li][k];
                    float4 v  = __ldg(eh + mo + c);
                    acc.x = fmaf(w, v.x, acc.x);
                    acc.y = fmaf(w, v.y, acc.y);
                    acc.z = fmaf(w, v.z, acc.z);
                    acc.w = fmaf(w, v.w, acc.w);
                }
            }
            // STS.128, lanes contiguous -> conflict-free
            *(float4*)&tile[li][4 * lane] = acc;
        }
        __syncthreads();

        // coalesced output: lane <-> l (128B lines); LDS side 4-way conflict, ok
        #pragma unroll
        for (int i = tid; i < DCHUNK * LTB; i += NTHRB) {
            int dd = i >> 5;          // 0..127
            int l  = i & (LTB - 1);
            outb[(size_t)(r * DCHUNK + dd) * L_ + l] = tile[l][dd];
        }
        __syncthreads();
    }
}

extern "C" void kernel_launch(void* const* d_in, const int* in_sizes, int n_in,
                              void* d_out, int out_size)
{
    const float* logits = (const float*)d_in[0];
    const float* e0     = (const float*)d_in[1];
    const float* e1     = (const float*)d_in[2];
    const float* e2     = (const float*)d_in[3];
    const float* e3     = (const float*)d_in[4];
    float*       out    = (float*)d_out;

    dim3 gridA(L_ / LTA, B_);   // 64 x 8 = 512 blocks
    topk_softmax<<<gridA, NTHRA>>>(logits);

    dim3 gridB(L_ / LTB, B_);   // 64 x 8 = 512 blocks
    gather_combine<<<gridB, NTHRB>>>(e0, e1, e2, e3, out);
}

// round 13
// speedup vs baseline: 1.7216x; 1.0245x over previous
#include <cuda_runtime.h>

// Problem constants (fixed by the dataset shapes)
#define B_      8
#define NHEADS  4
#define Q_      512      // codebook entries per head (N/4)
#define L_      2048     // sequence length (innermost logits dim)
#define D_      512      // embedding dim
#define K_      3        // top-k

// ---------------- kernel A config ----------------
#define LTA      32      // l-tile per block
#define NTHRA    512
#define SEGS     4       // n-range split per (h,l)
#define NSEG     (Q_ / SEGS)   // 128

// ---------------- kernel B config ----------------
#define LTB      32              // l-tile per block
#define NTHRB    256             // 8 warps
#define DCHUNK   128             // dd per round (float4: 32 lanes x 4)
#define NROUND   (D_ / DCHUNK)   // 4
#define TPITCH   132             // tile pitch in floats (16B-aligned)

// Scratch: (idx pre-scaled to float4 row base, w) per (b,h,l,k). 1.5 MB total.
__device__ int   g_idx[B_ * NHEADS * L_ * K_];
__device__ float g_w  [B_ * NHEADS * L_ * K_];

// top-3 update, branch-light common path (v <= t2 almost always)
#define TOP3_UPDATE(v, n)                                              \
    do {                                                               \
        if ((v) > t2) {                                                \
            if ((v) > t0)      { t2=t1; i2=i1; t1=t0; i1=i0; t0=(v); i0=(n); } \
            else if ((v) > t1) { t2=t1; i2=i1; t1=(v); i1=(n); }       \
            else               { t2=(v); i2=(n); }                     \
        }                                                              \
    } while (0)

// ======================= kernel A: top-3 + softmax =======================
__global__ __launch_bounds__(NTHRA)
void topk_softmax(const float* __restrict__ logits)
{
    const int b   = blockIdx.y;
    const int l0  = blockIdx.x * LTA;
    const int tid = threadIdx.x;

    // partial top-3 from segments 1..3 (segment 0 stays in the merger's regs)
    __shared__ float s_pv[SEGS - 1][NHEADS][LTA][K_];
    __shared__ int   s_pi[SEGS - 1][NHEADS][LTA][K_];

    const int l   = tid & (LTA - 1);           // 0..31
    const int h   = (tid >> 5) & (NHEADS - 1); // 0..3
    const int seg = tid >> 7;                  // 0..3
    const int nb  = seg * NSEG;

    const float* p = logits
        + ((size_t)b * (NHEADS * Q_) + (size_t)h * Q_ + nb) * L_ + l0 + l;

    float t0 = -3.4e38f, t1 = -3.4e38f, t2 = -3.4e38f;
    int   i0 = 0, i1 = 0, i2 = 0;

    // 8 loads per iter with CONSTANT offsets (j*L_*4 <= 57344 B fits the LDG
    // immediate) + one pointer bump: kills per-load IMAD address math.
    for (int n = 0; n < NSEG; n += 8) {
        float v0 = __ldg(p + 0 * L_);
        float v1 = __ldg(p + 1 * L_);
        float v2 = __ldg(p + 2 * L_);
        float v3 = __ldg(p + 3 * L_);
        float v4 = __ldg(p + 4 * L_);
        float v5 = __ldg(p + 5 * L_);
        float v6 = __ldg(p + 6 * L_);
        float v7 = __ldg(p + 7 * L_);
        p += 8 * L_;
        TOP3_UPDATE(v0, nb + n + 0);
        TOP3_UPDATE(v1, nb + n + 1);
        TOP3_UPDATE(v2, nb + n + 2);
        TOP3_UPDATE(v3, nb + n + 3);
        TOP3_UPDATE(v4, nb + n + 4);
        TOP3_UPDATE(v5, nb + n + 5);
        TOP3_UPDATE(v6, nb + n + 6);
        TOP3_UPDATE(v7, nb + n + 7);
    }

    if (seg > 0) {
        s_pv[seg - 1][h][l][0] = t0;  s_pi[seg - 1][h][l][0] = i0;
        s_pv[seg - 1][h][l][1] = t1;  s_pi[seg - 1][h][l][1] = i1;
        s_pv[seg - 1][h][l][2] = t2;  s_pi[seg - 1][h][l][2] = i2;
    }
    __syncthreads();

    if (seg == 0) {
        #pragma unroll
        for (int s = 0; s < SEGS - 1; s++) {
            #pragma unroll
            for (int k = 0; k < K_; k++) {
                float v = s_pv[s][h][l][k];
                int   n = s_pi[s][h][l][k];
                TOP3_UPDATE(v, n);
            }
        }
        float w1  = expf(t1 - t0);
        float w2  = expf(t2 - t0);
        float inv = 1.0f / (1.0f + w1 + w2);

        size_t base = (((size_t)b * NHEADS + h) * L_ + (l0 + l)) * K_;
        g_w[base + 0] = inv;
        g_w[base + 1] = w1 * inv;
        g_w[base + 2] = w2 * inv;
        // pre-scale index to float4-row offset (row = m * D_/4)
        g_idx[base + 0] = i0 * (D_ / 4);
        g_idx[base + 1] = i1 * (D_ / 4);
        g_idx[base + 2] = i2 * (D_ / 4);
    }
}

// =============== kernel B: gather-combine + transpose-out ===============
// launch_bounds(,4): cap regs ~64 so 4 blocks/SM fit -> 512 blocks in ONE wave
// (R12 ran regs=80 -> 3 blocks/SM -> 1.15 waves, 68-block tail).
__global__ __launch_bounds__(NTHRB, 4)
void gather_combine(const float* __restrict__ e0,
                    const float* __restrict__ e1,
                    const float* __restrict__ e2,
                    const float* __restrict__ e3,
                    float* __restrict__ out)
{
    const int b   = blockIdx.y;
    const int l0  = blockIdx.x * LTB;
    const int tid = threadIdx.x;

    __shared__ int   s_idx[NHEADS][LTB][K_];     // 384 ints
    __shared__ float s_w  [NHEADS][LTB][K_];     // 384 floats
    __shared__ __align__(16) float tile[LTB][TPITCH];

    // stage this block's (idx, w): 384 entries, strided over 256 threads
    for (int i = tid; i < NHEADS * LTB * K_; i += NTHRB) {
        int h  = i / (LTB * K_);
        int r  = i - h * (LTB * K_);
        size_t g = (((size_t)b * NHEADS + h) * L_ + l0) * K_ + r;
        ((int*)  s_idx)[i] = g_idx[g];
        ((float*)s_w  )[i] = g_w  [g];
    }
    __syncthreads();

    const int warp = tid >> 5;   // 0..7
    const int lane = tid & 31;
    float* outb = out + (size_t)b * D_ * L_ + l0;

    #pragma unroll
    for (int r = 0; r < NROUND; r++) {
        const int c = r * (DCHUNK / 4) + lane;   // float4 column

        // one li at a time: 12 LDG.128 in flight per warp (ample MLP),
        // keeps live registers bounded for the 4-blocks/SM target
        #pragma unroll 1
        for (int li = warp; li < LTB; li += NTHRB / 32) {
            float4 acc = make_float4(0.f, 0.f, 0.f, 0.f);
            #pragma unroll
            for (int h = 0; h < NHEADS; h++) {
                const float4* eh = (h == 0) ? (const float4*)e0
                                 : (h == 1) ? (const float4*)e1
                                 : (h == 2) ? (const float4*)e2
                                 :            (const float4*)e3;
                #pragma unroll
                for (int k = 0; k < K_; k++) {
                    int    mo = s_idx[h][li][k];    // already * D_/4
                    float  w  = s_w  [h][li][k];
                    float4 v  = __ldg(eh + mo + c);
                    acc.x = fmaf(w, v.x, acc.x);
                    acc.y = fmaf(w, v.y, acc.y);
                    acc.z = fmaf(w, v.z, acc.z);
                    acc.w = fmaf(w, v.w, acc.w);
                }
            }
            // STS.128, lanes contiguous -> conflict-free
            *(float4*)&tile[li][4 * lane] = acc;
        }
        __syncthreads();

        // coalesced output: lane <-> l (128B lines); LDS side 4-way conflict, ok
        #pragma unroll
        for (int i = tid; i < DCHUNK * LTB; i += NTHRB) {
            int dd = i >> 5;          // 0..127
            int l  = i & (LTB - 1);
            outb[(size_t)(r * DCHUNK + dd) * L_ + l] = tile[l][dd];
        }
        __syncthreads();
    }
}

extern "C" void kernel_launch(void* const* d_in, const int* in_sizes, int n_in,
                              void* d_out, int out_size)
{
    const float* logits = (const float*)d_in[0];
    const float* e0     = (const float*)d_in[1];
    const float* e1     = (const float*)d_in[2];
    const float* e2     = (const float*)d_in[3];
    const float* e3     = (const float*)d_in[4];
    float*       out    = (float*)d_out;

    dim3 gridA(L_ / LTA, B_);   // 64 x 8 = 512 blocks
    topk_softmax<<<gridA, NTHRA>>>(logits);

    dim3 gridB(L_ / LTB, B_);   // 64 x 8 = 512 blocks
    gather_combine<<<gridB, NTHRB>>>(e0, e1, e2, e3, out);
}

// round 14
// speedup vs baseline: 1.7295x; 1.0046x over previous
#include <cuda_runtime.h>

// Problem constants (fixed by the dataset shapes)
#define B_      8
#define NHEADS  4
#define Q_      512      // codebook entries per head (N/4)
#define L_      2048     // sequence length (innermost logits dim)
#define D_      512      // embedding dim
#define K_      3        // top-k

// ---------------- kernel A config ----------------
#define LTA      32      // l-tile per block
#define NTHRA    512
#define SEGS     4       // n-range split per (h,l)
#define NSEG     (Q_ / SEGS)   // 128

// ---------------- kernel B config ----------------
#define LTB      32              // l-tile per block
#define NTHRB    256             // 8 warps
#define DCHUNK   128             // dd per round (float4: 32 lanes x 4)
#define NROUND   (D_ / DCHUNK)   // 4
#define TPITCH   132             // tile pitch in floats (16B-aligned)

// Scratch: (idx pre-scaled to float4 row base, w) per (b,h,l,k). 1.5 MB total.
__device__ int   g_idx[B_ * NHEADS * L_ * K_];
__device__ float g_w  [B_ * NHEADS * L_ * K_];

// top-3 update, branch-light common path (v <= t2 almost always)
#define TOP3_UPDATE(v, n)                                              \
    do {                                                               \
        if ((v) > t2) {                                                \
            if ((v) > t0)      { t2=t1; i2=i1; t1=t0; i1=i0; t0=(v); i0=(n); } \
            else if ((v) > t1) { t2=t1; i2=i1; t1=(v); i1=(n); }       \
            else               { t2=(v); i2=(n); }                     \
        }                                                              \
    } while (0)

// ======================= kernel A: top-3 + softmax =======================
__global__ __launch_bounds__(NTHRA)
void topk_softmax(const float* __restrict__ logits)
{
    const int b   = blockIdx.y;
    const int l0  = blockIdx.x * LTA;
    const int tid = threadIdx.x;

    // partial top-3 from segments 1..3 (segment 0 stays in the merger's regs)
    __shared__ float s_pv[SEGS - 1][NHEADS][LTA][K_];
    __shared__ int   s_pi[SEGS - 1][NHEADS][LTA][K_];

    const int l   = tid & (LTA - 1);           // 0..31
    const int h   = (tid >> 5) & (NHEADS - 1); // 0..3
    const int seg = tid >> 7;                  // 0..3
    const int nb  = seg * NSEG;

    const float* p = logits
        + ((size_t)b * (NHEADS * Q_) + (size_t)h * Q_ + nb) * L_ + l0 + l;

    float t0 = -3.4e38f, t1 = -3.4e38f, t2 = -3.4e38f;
    int   i0 = 0, i1 = 0, i2 = 0;

    // 8 loads per iter with CONSTANT offsets (j*L_*4 <= 57344 B fits the LDG
    // immediate) + one pointer bump: kills per-load IMAD address math.
    for (int n = 0; n < NSEG; n += 8) {
        float v0 = __ldg(p + 0 * L_);
        float v1 = __ldg(p + 1 * L_);
        float v2 = __ldg(p + 2 * L_);
        float v3 = __ldg(p + 3 * L_);
        float v4 = __ldg(p + 4 * L_);
        float v5 = __ldg(p + 5 * L_);
        float v6 = __ldg(p + 6 * L_);
        float v7 = __ldg(p + 7 * L_);
        p += 8 * L_;
        TOP3_UPDATE(v0, nb + n + 0);
        TOP3_UPDATE(v1, nb + n + 1);
        TOP3_UPDATE(v2, nb + n + 2);
        TOP3_UPDATE(v3, nb + n + 3);
        TOP3_UPDATE(v4, nb + n + 4);
        TOP3_UPDATE(v5, nb + n + 5);
        TOP3_UPDATE(v6, nb + n + 6);
        TOP3_UPDATE(v7, nb + n + 7);
    }

    if (seg > 0) {
        s_pv[seg - 1][h][l][0] = t0;  s_pi[seg - 1][h][l][0] = i0;
        s_pv[seg - 1][h][l][1] = t1;  s_pi[seg - 1][h][l][1] = i1;
        s_pv[seg - 1][h][l][2] = t2;  s_pi[seg - 1][h][l][2] = i2;
    }
    __syncthreads();

    if (seg == 0) {
        #pragma unroll
        for (int s = 0; s < SEGS - 1; s++) {
            #pragma unroll
            for (int k = 0; k < K_; k++) {
                float v = s_pv[s][h][l][k];
                int   n = s_pi[s][h][l][k];
                TOP3_UPDATE(v, n);
            }
        }
        float w1  = expf(t1 - t0);
        float w2  = expf(t2 - t0);
        float inv = 1.0f / (1.0f + w1 + w2);

        size_t base = (((size_t)b * NHEADS + h) * L_ + (l0 + l)) * K_;
        g_w[base + 0] = inv;
        g_w[base + 1] = w1 * inv;
        g_w[base + 2] = w2 * inv;
        // pre-scale index to float4-row offset (row = m * D_/4)
        g_idx[base + 0] = i0 * (D_ / 4);
        g_idx[base + 1] = i1 * (D_ / 4);
        g_idx[base + 2] = i2 * (D_ / 4);
    }
}

// =============== kernel B: gather-combine + transpose-out ===============
// launch_bounds(,4): cap regs ~64 so 4 blocks/SM fit -> 512 blocks in ONE wave
// (R12 ran regs=80 -> 3 blocks/SM -> 1.15 waves, 68-block tail).
__global__ __launch_bounds__(NTHRB, 4)
void gather_combine(const float* __restrict__ e0,
                    const float* __restrict__ e1,
                    const float* __restrict__ e2,
                    const float* __restrict__ e3,
                    float* __restrict__ out)
{
    const int b   = blockIdx.y;
    const int l0  = blockIdx.x * LTB;
    const int tid = threadIdx.x;

    __shared__ int   s_idx[NHEADS][LTB][K_];     // 384 ints
    __shared__ float s_w  [NHEADS][LTB][K_];     // 384 floats
    __shared__ __align__(16) float tile[LTB][TPITCH];

    // stage this block's (idx, w): 384 entries, strided over 256 threads
    for (int i = tid; i < NHEADS * LTB * K_; i += NTHRB) {
        int h  = i / (LTB * K_);
        int r  = i - h * (LTB * K_);
        size_t g = (((size_t)b * NHEADS + h) * L_ + l0) * K_ + r;
        ((int*)  s_idx)[i] = g_idx[g];
        ((float*)s_w  )[i] = g_w  [g];
    }
    __syncthreads();

    const int warp = tid >> 5;   // 0..7
    const int lane = tid & 31;
    float* outb = out + (size_t)b * D_ * L_ + l0;

    #pragma unroll
    for (int r = 0; r < NROUND; r++) {
        const int c = r * (DCHUNK / 4) + lane;   // float4 column

        // one li at a time: 12 LDG.128 in flight per warp (ample MLP),
        // keeps live registers bounded for the 4-blocks/SM target
        #pragma unroll 1
        for (int li = warp; li < LTB; li += NTHRB / 32) {
            float4 acc = make_float4(0.f, 0.f, 0.f, 0.f);
            #pragma unroll
            for (int h = 0; h < NHEADS; h++) {
                const float4* eh = (h == 0) ? (const float4*)e0
                                 : (h == 1) ? (const float4*)e1
                                 : (h == 2) ? (const float4*)e2
                                 :            (const float4*)e3;
                #pragma unroll
                for (int k = 0; k < K_; k++) {
                    int    mo = s_idx[h][li][k];    // already * D_/4
                    float  w  = s_w  [h][li][k];
                    float4 v  = __ldg(eh + mo + c);
                    acc.x = fmaf(w, v.x, acc.x);
                    acc.y = fmaf(w, v.y, acc.y);
                    acc.z = fmaf(w, v.z, acc.z);
                    acc.w = fmaf(w, v.w, acc.w);
                }
            }
            // STS.128, lanes contiguous -> conflict-free
            *(float4*)&tile[li][4 * lane] = acc;
        }
        __syncthreads();

        // coalesced output: lane <-> l (128B lines); LDS side 4-way conflict, ok
        #pragma unroll
        for (int i = tid; i < DCHUNK * LTB; i += NTHRB) {
            int dd = i >> 5;          // 0..127
            int l  = i & (LTB - 1);
            outb[(size_t)(r * DCHUNK + dd) * L_ + l] = tile[l][dd];
        }
        __syncthreads();
    }
}

extern "C" void kernel_launch(void* const* d_in, const int* in_sizes, int n_in,
                              void* d_out, int out_size)
{
    const float* logits = (const float*)d_in[0];
    const float* e0     = (const float*)d_in[1];
    const float* e1     = (const float*)d_in[2];
    const float* e2     = (const float*)d_in[3];
    const float* e3     = (const float*)d_in[4];
    float*       out    = (float*)d_out;

    dim3 gridA(L_ / LTA, B_);   // 64 x 8 = 512 blocks
    topk_softmax<<<gridA, NTHRA>>>(logits);

    dim3 gridB(L_ / LTB, B_);   // 64 x 8 = 512 blocks
    gather_combine<<<gridB, NTHRB>>>(e0, e1, e2, e3, out);
}

// round 15
// speedup vs baseline: 1.8376x; 1.0625x over previous
#include <cuda_runtime.h>

// Problem constants (fixed by the dataset shapes)
#define B_      8
#define NHEADS  4
#define Q_      512      // codebook entries per head (N/4)
#define L_      2048     // sequence length (innermost logits dim)
#define D_      512      // embedding dim
#define K_      3        // top-k

// ---------------- kernel A config ----------------
#define LTA      32      // l-tile per block
#define NTHRA    512
#define SEGS     4       // n-range split per (h,l)
#define NSEG     (Q_ / SEGS)   // 128

// ---------------- kernel B config ----------------
#define LTB      32              // l-tile per block
#define NTHRB    256             // 8 warps
#define DCHUNK   128             // dd per round (float4: 32 lanes x 4)
#define NROUND   (D_ / DCHUNK)   // 4
#define TPITCH   132             // tile pitch: 33 float4s; 33 mod 32 = 1 ->
                                 // column-wise float4 reads are conflict-free

// Scratch: (idx pre-scaled to float4 row base, w) per (b,h,l,k). 1.5 MB total.
__device__ int   g_idx[B_ * NHEADS * L_ * K_];
__device__ float g_w  [B_ * NHEADS * L_ * K_];

// top-3 update, branch-light common path (v <= t2 almost always)
#define TOP3_UPDATE(v, n)                                              \
    do {                                                               \
        if ((v) > t2) {                                                \
            if ((v) > t0)      { t2=t1; i2=i1; t1=t0; i1=i0; t0=(v); i0=(n); } \
            else if ((v) > t1) { t2=t1; i2=i1; t1=(v); i1=(n); }       \
            else               { t2=(v); i2=(n); }                     \
        }                                                              \
    } while (0)

// ======================= kernel A: top-3 + softmax =======================
__global__ __launch_bounds__(NTHRA)
void topk_softmax(const float* __restrict__ logits)
{
    const int b   = blockIdx.y;
    const int l0  = blockIdx.x * LTA;
    const int tid = threadIdx.x;

    // partial top-3 from segments 1..3 (segment 0 stays in the merger's regs)
    __shared__ float s_pv[SEGS - 1][NHEADS][LTA][K_];
    __shared__ int   s_pi[SEGS - 1][NHEADS][LTA][K_];

    const int l   = tid & (LTA - 1);           // 0..31
    const int h   = (tid >> 5) & (NHEADS - 1); // 0..3
    const int seg = tid >> 7;                  // 0..3
    const int nb  = seg * NSEG;

    const float* p = logits
        + ((size_t)b * (NHEADS * Q_) + (size_t)h * Q_ + nb) * L_ + l0 + l;

    float t0 = -3.4e38f, t1 = -3.4e38f, t2 = -3.4e38f;
    int   i0 = 0, i1 = 0, i2 = 0;

    // 8 loads per iter with CONSTANT offsets (fits LDG immediate) + one
    // pointer bump: no per-load address IMADs.
    for (int n = 0; n < NSEG; n += 8) {
        float v0 = __ldg(p + 0 * L_);
        float v1 = __ldg(p + 1 * L_);
        float v2 = __ldg(p + 2 * L_);
        float v3 = __ldg(p + 3 * L_);
        float v4 = __ldg(p + 4 * L_);
        float v5 = __ldg(p + 5 * L_);
        float v6 = __ldg(p + 6 * L_);
        float v7 = __ldg(p + 7 * L_);
        p += 8 * L_;
        TOP3_UPDATE(v0, nb + n + 0);
        TOP3_UPDATE(v1, nb + n + 1);
        TOP3_UPDATE(v2, nb + n + 2);
        TOP3_UPDATE(v3, nb + n + 3);
        TOP3_UPDATE(v4, nb + n + 4);
        TOP3_UPDATE(v5, nb + n + 5);
        TOP3_UPDATE(v6, nb + n + 6);
        TOP3_UPDATE(v7, nb + n + 7);
    }

    if (seg > 0) {
        s_pv[seg - 1][h][l][0] = t0;  s_pi[seg - 1][h][l][0] = i0;
        s_pv[seg - 1][h][l][1] = t1;  s_pi[seg - 1][h][l][1] = i1;
        s_pv[seg - 1][h][l][2] = t2;  s_pi[seg - 1][h][l][2] = i2;
    }
    __syncthreads();

    if (seg == 0) {
        #pragma unroll
        for (int s = 0; s < SEGS - 1; s++) {
            #pragma unroll
            for (int k = 0; k < K_; k++) {
                float v = s_pv[s][h][l][k];
                int   n = s_pi[s][h][l][k];
                TOP3_UPDATE(v, n);
            }
        }
        float w1  = expf(t1 - t0);
        float w2  = expf(t2 - t0);
        float inv = 1.0f / (1.0f + w1 + w2);

        size_t base = (((size_t)b * NHEADS + h) * L_ + (l0 + l)) * K_;
        g_w[base + 0] = inv;
        g_w[base + 1] = w1 * inv;
        g_w[base + 2] = w2 * inv;
        // pre-scale index to float4-row offset (row = m * D_/4)
        g_idx[base + 0] = i0 * (D_ / 4);
        g_idx[base + 1] = i1 * (D_ / 4);
        g_idx[base + 2] = i2 * (D_ / 4);
    }
}

// =============== kernel B: gather-combine + transpose-out ===============
__global__ __launch_bounds__(NTHRB, 4)
void gather_combine(const float* __restrict__ e0,
                    const float* __restrict__ e1,
                    const float* __restrict__ e2,
                    const float* __restrict__ e3,
                    float* __restrict__ out)
{
    const int b   = blockIdx.y;
    const int l0  = blockIdx.x * LTB;
    const int tid = threadIdx.x;

    __shared__ int   s_idx[NHEADS][LTB][K_];     // 384 ints
    __shared__ float s_w  [NHEADS][LTB][K_];     // 384 floats
    __shared__ __align__(16) float tile[LTB][TPITCH];

    // stage this block's (idx, w): 384 entries, strided over 256 threads
    for (int i = tid; i < NHEADS * LTB * K_; i += NTHRB) {
        int h  = i / (LTB * K_);
        int r  = i - h * (LTB * K_);
        size_t g = (((size_t)b * NHEADS + h) * L_ + l0) * K_ + r;
        ((int*)  s_idx)[i] = g_idx[g];
        ((float*)s_w  )[i] = g_w  [g];
    }
    __syncthreads();

    const int warp = tid >> 5;   // 0..7
    const int lane = tid & 31;
    float* outb = out + (size_t)b * D_ * L_ + l0;

    #pragma unroll
    for (int r = 0; r < NROUND; r++) {
        const int c = r * (DCHUNK / 4) + lane;   // float4 column

        // one li at a time: 12 LDG.128 in flight per warp (ample MLP),
        // bounded live registers for the 4-blocks/SM target
        #pragma unroll 1
        for (int li = warp; li < LTB; li += NTHRB / 32) {
            float4 acc = make_float4(0.f, 0.f, 0.f, 0.f);
            #pragma unroll
            for (int h = 0; h < NHEADS; h++) {
                const float4* eh = (h == 0) ? (const float4*)e0
                                 : (h == 1) ? (const float4*)e1
                                 : (h == 2) ? (const float4*)e2
                                 :            (const float4*)e3;
                #pragma unroll
                for (int k = 0; k < K_; k++) {
                    int    mo = s_idx[h][li][k];    // already * D_/4
                    float  w  = s_w  [h][li][k];
                    float4 v  = __ldg(eh + mo + c);
                    acc.x = fmaf(w, v.x, acc.x);
                    acc.y = fmaf(w, v.y, acc.y);
                    acc.z = fmaf(w, v.z, acc.z);
                    acc.w = fmaf(w, v.w, acc.w);
                }
            }
            // STS.128, lanes contiguous -> conflict-free
            *(float4*)&tile[li][4 * lane] = acc;
        }
        __syncthreads();

        // write-out: lane <-> l, warp <-> float4 dd-group.
        // LDS.128 at float4 addr l*33 + j: lane stride 33 = 1 (mod 32)
        // -> CONFLICT-FREE (R14 scalar version was 4-way conflicted).
        // Each thread then emits 4 coalesced STG.32 (128B lines along l).
        #pragma unroll
        for (int it = 0; it < (DCHUNK / 4) * LTB / NTHRB; it++) {   // 4 iters
            int i = tid + it * NTHRB;
            int l = i & (LTB - 1);        // lane == l
            int j = i >> 5;               // float4 group 0..31
            float4 v = *(const float4*)&tile[l][4 * j];
            size_t dbase = (size_t)(r * DCHUNK + 4 * j) * L_ + l;
            outb[dbase + 0 * L_] = v.x;
            outb[dbase + 1 * L_] = v.y;
            outb[dbase + 2 * L_] = v.z;
            outb[dbase + 3 * L_] = v.w;
        }
        __syncthreads();
    }
}

extern "C" void kernel_launch(void* const* d_in, const int* in_sizes, int n_in,
                              void* d_out, int out_size)
{
    const float* logits = (const float*)d_in[0];
    const float* e0     = (const float*)d_in[1];
    const float* e1     = (const float*)d_in[2];
    const float* e2     = (const float*)d_in[3];
    const float* e3     = (const float*)d_in[4];
    float*       out    = (float*)d_out;

    dim3 gridA(L_ / LTA, B_);   // 64 x 8 = 512 blocks
    topk_softmax<<<gridA, NTHRA>>>(logits);

    dim3 gridB(L_ / LTB, B_);   // 64 x 8 = 512 blocks
    gather_combine<<<gridB, NTHRB>>>(e0, e1, e2, e3, out);
}